// round 16
// baseline (speedup 1.0000x reference)
#include <cuda_runtime.h>
#include <cuda_bf16.h>
#include <cstdint>

#define NCLS   5000
#define NV4    1250      // 5000 / 4
#define LVLS   4
#define NB     4096
#define NROWS  (NB * LVLS)   // 16384
#define BLK    512           // wider block -> shorter block duration
#define NCH    3             // float4 chunks per thread (512*2=1024, +226)
#define RPB    4             // rows per block == LVLS: block b == batch item b
#define GRID1  (NROWS / RPB) // 4096
#define NW     (BLK / 32)    // 16 warps

#define L2E    1.4426950408889634f   // log2(e)
#define LN2    0.6931471805599453f

// Scratch: one float2 partial per block {weighted_ce, weighted_count}
__device__ __align__(16) float2 g_part[GRID1];

__device__ __forceinline__ float ex2(float x) {
    float y;
    asm("ex2.approx.ftz.f32 %0, %1;" : "=f"(y) : "f"(x));
    return y;
}

// ---------------------------------------------------------------------------
// Kernel 1: per-batch-item softmax stats + fused H-consistency epilogue.
// Same algorithm as the converged R13/R15 kernel; BLK 256 -> 512 so each
// block finishes in half the time (halves the last-wave drain).
// ---------------------------------------------------------------------------
__global__ __launch_bounds__(BLK, 2)
void row_stats_kernel(const float* __restrict__ y_pred,
                      const int*   __restrict__ y_true,
                      const float* __restrict__ H)
{
    const int tid  = threadIdx.x;
    const int row0 = blockIdx.x * RPB;

    __shared__ float sh_xt[RPB];
    __shared__ float sh_m[NW];
    __shared__ float sh_s[NW];
    __shared__ float sh_M, sh_S;
    __shared__ int   sh_idx[NW];

    // Resolve all target logits up front (dependent chain off the critical tail)
    if (tid < RPB) {
        int t = __ldg(y_true + row0 + tid);
        sh_xt[tid] = __ldg(y_pred + (size_t)(row0 + tid) * NCLS + t);
    }

    float4 buf[2][NCH];

    // Prefetch row 0
    {
        const float4* __restrict__ p =
            reinterpret_cast<const float4*>(y_pred + (size_t)row0 * NCLS);
        #pragma unroll
        for (int it = 0; it < NCH; ++it) {
            int i = tid + it * BLK;
            if (it < 2 || i < NV4) buf[0][it] = __ldcs(p + i);
            else buf[0][it] = make_float4(-1e30f, -1e30f, -1e30f, -1e30f);
        }
    }

    const unsigned full = 0xffffffffu;
    const int wid = tid >> 5, lane = tid & 31;

    int   am[RPB];     // thread 0: per-level argmax (registers, r unrolled)
    float cel[RPB];    // thread 0: per-level cross-entropy

    #pragma unroll
    for (int r = 0; r < RPB; ++r) {
        float4* v = buf[r & 1];

        // ---- prefetch next row (loads fly across the barriers below) ----
        if (r + 1 < RPB) {
            const float4* __restrict__ pn =
                reinterpret_cast<const float4*>(y_pred + (size_t)(row0 + r + 1) * NCLS);
            float4* w = buf[(r + 1) & 1];
            #pragma unroll
            for (int it = 0; it < NCH; ++it) {
                int i = tid + it * BLK;
                if (it < 2 || i < NV4) w[it] = __ldcs(pn + i);
                else w[it] = make_float4(-1e30f, -1e30f, -1e30f, -1e30f);
            }
        }

        // ---- Phase A: local max (pure FMNMX tree) ----
        float mloc = fmaxf(fmaxf(v[0].x, v[0].y), fmaxf(v[0].z, v[0].w));
        #pragma unroll
        for (int it = 1; it < NCH; ++it)
            mloc = fmaxf(mloc, fmaxf(fmaxf(v[it].x, v[it].y),
                                     fmaxf(v[it].z, v[it].w)));

        // ---- Phase B: sum exp2(x*L2E - ml), 4 accumulators ----
        const float ml = mloc * L2E;
        float s0 = 0.f, s1 = 0.f, s2 = 0.f, s3 = 0.f;
        #pragma unroll
        for (int it = 0; it < NCH; ++it) {
            s0 += ex2(fmaf(v[it].x, L2E, -ml));
            s1 += ex2(fmaf(v[it].y, L2E, -ml));
            s2 += ex2(fmaf(v[it].z, L2E, -ml));
            s3 += ex2(fmaf(v[it].w, L2E, -ml));
        }
        float s = (s0 + s1) + (s2 + s3);
        float m = mloc;

        // ---- warp reduce (m, s) ----
        #pragma unroll
        for (int off = 16; off; off >>= 1) {
            float om = __shfl_down_sync(full, m, off);
            float os = __shfl_down_sync(full, s, off);
            float nm = fmaxf(m, om);
            s = s * ex2((m - nm) * L2E) + os * ex2((om - nm) * L2E);
            m = nm;
        }
        if (lane == 0) { sh_m[wid] = m; sh_s[wid] = s; }
        __syncthreads();

        if (wid == 0) {
            m = (lane < NW) ? sh_m[lane] : -1e30f;
            s = (lane < NW) ? sh_s[lane] : 0.0f;
            #pragma unroll
            for (int off = 8; off; off >>= 1) {
                float om = __shfl_down_sync(full, m, off);
                float os = __shfl_down_sync(full, s, off);
                float nm = fmaxf(m, om);
                s = s * ex2((m - nm) * L2E) + os * ex2((om - nm) * L2E);
                m = nm;
            }
            if (lane == 0) { sh_M = m; sh_S = s; }
        }
        __syncthreads();

        // ---- argmax: equality rescan (signed INT_MAX sentinel — R6 lesson) ----
        const float M = sh_M;
        int idx = 0x7fffffff;
        if (mloc == M) {
            #pragma unroll
            for (int it = 0; it < NCH; ++it) {
                int gi = (tid + it * BLK) << 2;
                if (v[it].x == M) idx = min(idx, gi + 0);
                if (v[it].y == M) idx = min(idx, gi + 1);
                if (v[it].z == M) idx = min(idx, gi + 2);
                if (v[it].w == M) idx = min(idx, gi + 3);
            }
        }
        idx = __reduce_min_sync(full, idx);
        if (lane == 0) sh_idx[wid] = idx;
        __syncthreads();

        if (tid == 0) {
            int best = sh_idx[0];
            #pragma unroll
            for (int w = 1; w < NW; ++w) best = min(best, sh_idx[w]);
            am[r]  = best;
            cel[r] = fmaf(LN2, __log2f(sh_S), sh_M) - sh_xt[r];
        }
    }

    // ---- fused epilogue: H consistency probes for this batch item ----
    if (tid == 0) {
        float h1 = __ldg(H + (size_t)am[0] * NCLS + am[1]);
        float h2 = __ldg(H + (size_t)am[1] * NCLS + am[2]);
        float h3 = __ldg(H + (size_t)am[2] * NCLS + am[3]);
        float c1 = (h1 != 1.0f) ? 1.0f : 0.0f;
        float c2 = (h2 != 1.0f) ? 1.0f : 0.0f;
        float c3 = (h3 != 1.0f) ? 1.0f : 0.0f;
        float pcw = 0.25f * c1 + 0.15f * c2 + 0.10f * c3;
        float pce = 0.25f * cel[1] + 0.15f * cel[2] + 0.10f * cel[3];
        g_part[blockIdx.x] = make_float2(pce, pcw);
    }

    // PDL: partial stored — allow the dependent reduce grid to launch.
#if __CUDA_ARCH__ >= 900
    cudaTriggerProgrammaticLaunchCompletion();
#endif
}

// ---------------------------------------------------------------------------
// Kernel 2: deterministic reduction of 4096 float2 partials -> scalar loss.
// Launched via PDL: ramps up concurrently with kernel 1, waits on the grid
// dependency, then does 2 x LDG.128 per thread + fixed-order tree reduce.
// ---------------------------------------------------------------------------
__global__ __launch_bounds__(1024)
void final_reduce_kernel(float* __restrict__ out)
{
#if __CUDA_ARCH__ >= 900
    cudaGridDependencySynchronize();
#endif

    const int tid = threadIdx.x;
    const float4* __restrict__ gp4 = reinterpret_cast<const float4*>(g_part);

    // 2048 float4 total; thread t takes gp4[t] and gp4[t + 1024].
    float4 a = gp4[tid];
    float4 b = gp4[tid + 1024];
    float ace = (a.x + a.z) + (b.x + b.z);   // .x/.z = pce of two partials
    float acw = (a.y + a.w) + (b.y + b.w);   // .y/.w = pcw of two partials

    const unsigned full = 0xffffffffu;
    #pragma unroll
    for (int off = 16; off; off >>= 1) {
        ace += __shfl_down_sync(full, ace, off);
        acw += __shfl_down_sync(full, acw, off);
    }

    __shared__ float s_ce[32], s_cw[32];
    const int wid = tid >> 5, lane = tid & 31;
    if (lane == 0) { s_ce[wid] = ace; s_cw[wid] = acw; }
    __syncthreads();

    if (wid == 0) {
        float tce = s_ce[lane];
        float tcw = s_cw[lane];
        #pragma unroll
        for (int off = 16; off; off >>= 1) {
            tce += __shfl_down_sync(full, tce, off);
            tcw += __shfl_down_sync(full, tcw, off);
        }
        if (lane == 0) {
            const float E  = 2.718281828459045f;
            const float iB = 1.0f / (float)NB;
            out[0] = E * tcw + tce * iB;
        }
    }
}

// ---------------------------------------------------------------------------
extern "C" void kernel_launch(void* const* d_in, const int* in_sizes, int n_in,
                              void* d_out, int out_size)
{
    const float* y_pred = nullptr;
    const int*   y_true = nullptr;
    const float* H      = nullptr;
    for (int i = 0; i < n_in; ++i) {
        if (in_sizes[i] == NROWS * NCLS)      y_pred = (const float*)d_in[i];
        else if (in_sizes[i] == NROWS)        y_true = (const int*)d_in[i];
        else if (in_sizes[i] == NCLS * NCLS)  H      = (const float*)d_in[i];
    }

    row_stats_kernel<<<GRID1, BLK>>>(y_pred, y_true, H);

    // Dependent launch of the reduce with programmatic stream serialization:
    // its launch/ramp overlaps with row_stats execution.
    cudaLaunchConfig_t cfg = {};
    cfg.gridDim  = dim3(1, 1, 1);
    cfg.blockDim = dim3(1024, 1, 1);
    cfg.dynamicSmemBytes = 0;
    cfg.stream = 0;
    cudaLaunchAttribute attr[1];
    attr[0].id = cudaLaunchAttributeProgrammaticStreamSerialization;
    attr[0].val.programmaticStreamSerializationAllowed = 1;
    cfg.attrs = attr;
    cfg.numAttrs = 1;
    cudaLaunchKernelEx(&cfg, final_reduce_kernel, (float*)d_out);
}

// round 17
// speedup vs baseline: 1.3675x; 1.3675x over previous
#include <cuda_runtime.h>
#include <cuda_bf16.h>
#include <cstdint>

#define NCLS   5000
#define NV4    1250      // 5000 / 4
#define LVLS   4
#define NB     4096
#define NROWS  (NB * LVLS)   // 16384
#define BLK    256
#define RPB    4             // rows per block == LVLS: block b == batch item b
#define GRID1  (NROWS / RPB) // 4096

#define L2E    1.4426950408889634f   // log2(e)
#define LN2    0.6931471805599453f

// Scratch: one float2 partial per block {weighted_ce, weighted_count}
__device__ __align__(16) float2 g_part[GRID1];

__device__ __forceinline__ float ex2(float x) {
    float y;
    asm("ex2.approx.ftz.f32 %0, %1;" : "=f"(y) : "f"(x));
    return y;
}

// ---------------------------------------------------------------------------
// Kernel 1: per-batch-item softmax stats + fused H-consistency epilogue.
// Measured-best configuration (R15): BLK=256, RPB=4, register double-buffer,
// hoisted xt resolution, fused H probes, PDL trigger. ~51 us @ 82% DRAM.
// ---------------------------------------------------------------------------
__global__ __launch_bounds__(BLK, 4)
void row_stats_kernel(const float* __restrict__ y_pred,
                      const int*   __restrict__ y_true,
                      const float* __restrict__ H)
{
    const int tid  = threadIdx.x;
    const int row0 = blockIdx.x * RPB;

    __shared__ float sh_xt[RPB];
    __shared__ float sh_m[8];
    __shared__ float sh_s[8];
    __shared__ float sh_M, sh_S;
    __shared__ int   sh_idx[8];

    // Resolve all target logits up front (dependent chain off the critical tail)
    if (tid < RPB) {
        int t = __ldg(y_true + row0 + tid);
        sh_xt[tid] = __ldg(y_pred + (size_t)(row0 + tid) * NCLS + t);
    }

    float4 buf[2][5];

    // Prefetch row 0
    {
        const float4* __restrict__ p =
            reinterpret_cast<const float4*>(y_pred + (size_t)row0 * NCLS);
        #pragma unroll
        for (int it = 0; it < 5; ++it) {
            int i = tid + it * BLK;
            if (it < 4 || i < NV4) buf[0][it] = __ldcs(p + i);
            else buf[0][it] = make_float4(-1e30f, -1e30f, -1e30f, -1e30f);
        }
    }

    const unsigned full = 0xffffffffu;
    const int wid = tid >> 5, lane = tid & 31;

    int   am[RPB];     // thread 0: per-level argmax (registers, r unrolled)
    float cel[RPB];    // thread 0: per-level cross-entropy

    #pragma unroll
    for (int r = 0; r < RPB; ++r) {
        float4* v = buf[r & 1];

        // ---- prefetch next row (loads fly across the barriers below) ----
        if (r + 1 < RPB) {
            const float4* __restrict__ pn =
                reinterpret_cast<const float4*>(y_pred + (size_t)(row0 + r + 1) * NCLS);
            float4* w = buf[(r + 1) & 1];
            #pragma unroll
            for (int it = 0; it < 5; ++it) {
                int i = tid + it * BLK;
                if (it < 4 || i < NV4) w[it] = __ldcs(pn + i);
                else w[it] = make_float4(-1e30f, -1e30f, -1e30f, -1e30f);
            }
        }

        // ---- Phase A: local max (pure FMNMX tree) ----
        float mloc = fmaxf(fmaxf(v[0].x, v[0].y), fmaxf(v[0].z, v[0].w));
        #pragma unroll
        for (int it = 1; it < 5; ++it)
            mloc = fmaxf(mloc, fmaxf(fmaxf(v[it].x, v[it].y),
                                     fmaxf(v[it].z, v[it].w)));

        // ---- Phase B: sum exp2(x*L2E - ml), 4 accumulators ----
        const float ml = mloc * L2E;
        float s0 = 0.f, s1 = 0.f, s2 = 0.f, s3 = 0.f;
        #pragma unroll
        for (int it = 0; it < 5; ++it) {
            s0 += ex2(fmaf(v[it].x, L2E, -ml));
            s1 += ex2(fmaf(v[it].y, L2E, -ml));
            s2 += ex2(fmaf(v[it].z, L2E, -ml));
            s3 += ex2(fmaf(v[it].w, L2E, -ml));
        }
        float s = (s0 + s1) + (s2 + s3);
        float m = mloc;

        // ---- warp reduce (m, s) ----
        #pragma unroll
        for (int off = 16; off; off >>= 1) {
            float om = __shfl_down_sync(full, m, off);
            float os = __shfl_down_sync(full, s, off);
            float nm = fmaxf(m, om);
            s = s * ex2((m - nm) * L2E) + os * ex2((om - nm) * L2E);
            m = nm;
        }
        if (lane == 0) { sh_m[wid] = m; sh_s[wid] = s; }
        __syncthreads();

        if (wid == 0) {
            m = (lane < 8) ? sh_m[lane] : -1e30f;
            s = (lane < 8) ? sh_s[lane] : 0.0f;
            #pragma unroll
            for (int off = 4; off; off >>= 1) {
                float om = __shfl_down_sync(full, m, off);
                float os = __shfl_down_sync(full, s, off);
                float nm = fmaxf(m, om);
                s = s * ex2((m - nm) * L2E) + os * ex2((om - nm) * L2E);
                m = nm;
            }
            if (lane == 0) { sh_M = m; sh_S = s; }
        }
        __syncthreads();

        // ---- argmax: equality rescan (signed INT_MAX sentinel — R6 lesson) ----
        const float M = sh_M;
        int idx = 0x7fffffff;
        if (mloc == M) {
            #pragma unroll
            for (int it = 0; it < 5; ++it) {
                int gi = (tid + it * BLK) << 2;
                if (v[it].x == M) idx = min(idx, gi + 0);
                if (v[it].y == M) idx = min(idx, gi + 1);
                if (v[it].z == M) idx = min(idx, gi + 2);
                if (v[it].w == M) idx = min(idx, gi + 3);
            }
        }
        idx = __reduce_min_sync(full, idx);
        if (lane == 0) sh_idx[wid] = idx;
        __syncthreads();

        if (tid == 0) {
            int best = sh_idx[0];
            #pragma unroll
            for (int w = 1; w < 8; ++w) best = min(best, sh_idx[w]);
            am[r]  = best;
            cel[r] = fmaf(LN2, __log2f(sh_S), sh_M) - sh_xt[r];
        }
    }

    // ---- fused epilogue: H consistency probes for this batch item ----
    if (tid == 0) {
        float h1 = __ldg(H + (size_t)am[0] * NCLS + am[1]);
        float h2 = __ldg(H + (size_t)am[1] * NCLS + am[2]);
        float h3 = __ldg(H + (size_t)am[2] * NCLS + am[3]);
        float c1 = (h1 != 1.0f) ? 1.0f : 0.0f;
        float c2 = (h2 != 1.0f) ? 1.0f : 0.0f;
        float c3 = (h3 != 1.0f) ? 1.0f : 0.0f;
        float pcw = 0.25f * c1 + 0.15f * c2 + 0.10f * c3;
        float pce = 0.25f * cel[1] + 0.15f * cel[2] + 0.10f * cel[3];
        g_part[blockIdx.x] = make_float2(pce, pcw);
    }

    // PDL: partial stored — allow the dependent reduce grid to launch.
#if __CUDA_ARCH__ >= 900
    cudaTriggerProgrammaticLaunchCompletion();
#endif
}

// ---------------------------------------------------------------------------
// Kernel 2: deterministic reduction of 4096 float2 partials -> scalar loss.
// Launched via PDL: ramps up concurrently with kernel 1, waits on the grid
// dependency, then does 2 x LDG.128 per thread + fixed-order tree reduce.
// ---------------------------------------------------------------------------
__global__ __launch_bounds__(1024)
void final_reduce_kernel(float* __restrict__ out)
{
#if __CUDA_ARCH__ >= 900
    cudaGridDependencySynchronize();
#endif

    const int tid = threadIdx.x;
    const float4* __restrict__ gp4 = reinterpret_cast<const float4*>(g_part);

    // 2048 float4 total; thread t takes gp4[t] and gp4[t + 1024].
    float4 a = gp4[tid];
    float4 b = gp4[tid + 1024];
    float ace = (a.x + a.z) + (b.x + b.z);   // .x/.z = pce of two partials
    float acw = (a.y + a.w) + (b.y + b.w);   // .y/.w = pcw of two partials

    const unsigned full = 0xffffffffu;
    #pragma unroll
    for (int off = 16; off; off >>= 1) {
        ace += __shfl_down_sync(full, ace, off);
        acw += __shfl_down_sync(full, acw, off);
    }

    __shared__ float s_ce[32], s_cw[32];
    const int wid = tid >> 5, lane = tid & 31;
    if (lane == 0) { s_ce[wid] = ace; s_cw[wid] = acw; }
    __syncthreads();

    if (wid == 0) {
        float tce = s_ce[lane];
        float tcw = s_cw[lane];
        #pragma unroll
        for (int off = 16; off; off >>= 1) {
            tce += __shfl_down_sync(full, tce, off);
            tcw += __shfl_down_sync(full, tcw, off);
        }
        if (lane == 0) {
            const float E  = 2.718281828459045f;
            const float iB = 1.0f / (float)NB;
            out[0] = E * tcw + tce * iB;
        }
    }
}

// ---------------------------------------------------------------------------
extern "C" void kernel_launch(void* const* d_in, const int* in_sizes, int n_in,
                              void* d_out, int out_size)
{
    const float* y_pred = nullptr;
    const int*   y_true = nullptr;
    const float* H      = nullptr;
    for (int i = 0; i < n_in; ++i) {
        if (in_sizes[i] == NROWS * NCLS)      y_pred = (const float*)d_in[i];
        else if (in_sizes[i] == NROWS)        y_true = (const int*)d_in[i];
        else if (in_sizes[i] == NCLS * NCLS)  H      = (const float*)d_in[i];
    }

    row_stats_kernel<<<GRID1, BLK>>>(y_pred, y_true, H);

    // Dependent launch of the reduce with programmatic stream serialization:
    // its launch/ramp overlaps with row_stats execution.
    cudaLaunchConfig_t cfg = {};
    cfg.gridDim  = dim3(1, 1, 1);
    cfg.blockDim = dim3(1024, 1, 1);
    cfg.dynamicSmemBytes = 0;
    cfg.stream = 0;
    cudaLaunchAttribute attr[1];
    attr[0].id = cudaLaunchAttributeProgrammaticStreamSerialization;
    attr[0].val.programmaticStreamSerializationAllowed = 1;
    cfg.attrs = attr;
    cfg.numAttrs = 1;
    cudaLaunchKernelEx(&cfg, final_reduce_kernel, (float*)d_out);
}